// round 3
// baseline (speedup 1.0000x reference)
#include <cuda_runtime.h>
#include <math.h>

#define H 1024
#define V 50257
#define L 4096

// ---------------- device scratch (no allocations allowed) ----------------
__device__ float g_concat[2 * H];   // [0..H) = ctx (atomically accumulated), [H..2H) = h_new
__device__ float g_scores[L];
__device__ float g_attn[L];
__device__ float g_part[128];       // 64 (max, sumexp) pairs
__device__ float g_lse;

// ---------------- helpers ----------------
__device__ __forceinline__ float warp_sum(float v) {
#pragma unroll
    for (int o = 16; o > 0; o >>= 1) v += __shfl_down_sync(0xFFFFFFFFu, v, o);
    return v;
}
__device__ __forceinline__ float warp_max(float v) {
#pragma unroll
    for (int o = 16; o > 0; o >>= 1) v = fmaxf(v, __shfl_down_sync(0xFFFFFFFFu, v, o));
    return v;
}

// ---------------- 1) GRU cell: one block per output element j (float4 loads) --------
__global__ void __launch_bounds__(128) gru_kernel(
    const int* __restrict__ inp, const float* __restrict__ hidden,
    const float* __restrict__ embedding,
    const float* __restrict__ w_ih, const float* __restrict__ w_hh,
    const float* __restrict__ b_ih, const float* __restrict__ b_hh,
    float* __restrict__ out_h)
{
    __shared__ float4 xs[H / 4];
    __shared__ float4 hs[H / 4];
    __shared__ float red[6][4];
    const int j = blockIdx.x;
    const int tid = threadIdx.x;
    const int idx = inp[0];   // low 32 bits of the (int64) token id — LE safe

    const float4* emb4 = (const float4*)(embedding + (size_t)idx * H);
    const float4* hid4 = (const float4*)hidden;
    xs[tid]       = emb4[tid];        xs[tid + 128] = emb4[tid + 128];
    hs[tid]       = hid4[tid];        hs[tid + 128] = hid4[tid + 128];
    __syncthreads();

    const float4* wi0 = (const float4*)(w_ih + (size_t)j * H);
    const float4* wi1 = (const float4*)(w_ih + (size_t)(j + H) * H);
    const float4* wi2 = (const float4*)(w_ih + (size_t)(j + 2 * H) * H);
    const float4* wh0 = (const float4*)(w_hh + (size_t)j * H);
    const float4* wh1 = (const float4*)(w_hh + (size_t)(j + H) * H);
    const float4* wh2 = (const float4*)(w_hh + (size_t)(j + 2 * H) * H);

    float a0 = 0.f, a1 = 0.f, a2 = 0.f, a3 = 0.f, a4 = 0.f, a5 = 0.f;
#pragma unroll
    for (int p = 0; p < 2; p++) {
        const int k = tid + 128 * p;
        const float4 xv = xs[k], hv = hs[k];
        float4 w;
        w = wi0[k]; a0 += w.x * xv.x + w.y * xv.y + w.z * xv.z + w.w * xv.w;
        w = wi1[k]; a1 += w.x * xv.x + w.y * xv.y + w.z * xv.z + w.w * xv.w;
        w = wi2[k]; a2 += w.x * xv.x + w.y * xv.y + w.z * xv.z + w.w * xv.w;
        w = wh0[k]; a3 += w.x * hv.x + w.y * hv.y + w.z * hv.z + w.w * hv.w;
        w = wh1[k]; a4 += w.x * hv.x + w.y * hv.y + w.z * hv.z + w.w * hv.w;
        w = wh2[k]; a5 += w.x * hv.x + w.y * hv.y + w.z * hv.z + w.w * hv.w;
    }
    a0 = warp_sum(a0); a1 = warp_sum(a1); a2 = warp_sum(a2);
    a3 = warp_sum(a3); a4 = warp_sum(a4); a5 = warp_sum(a5);
    const int warp = tid >> 5, lane = tid & 31;
    if (lane == 0) {
        red[0][warp] = a0; red[1][warp] = a1; red[2][warp] = a2;
        red[3][warp] = a3; red[4][warp] = a4; red[5][warp] = a5;
    }
    __syncthreads();
    if (tid == 0) {
        float s[6];
#pragma unroll
        for (int q = 0; q < 6; q++) s[q] = red[q][0] + red[q][1] + red[q][2] + red[q][3];
        const float i_r = s[0] + b_ih[j];
        const float i_z = s[1] + b_ih[j + H];
        const float i_n = s[2] + b_ih[j + 2 * H];
        const float h_r = s[3] + b_hh[j];
        const float h_z = s[4] + b_hh[j + H];
        const float h_n = s[5] + b_hh[j + 2 * H];
        const float r = 1.f / (1.f + __expf(-(i_r + h_r)));
        const float z = 1.f / (1.f + __expf(-(i_z + h_z)));
        const float n = tanhf(i_n + r * h_n);
        const float hj = ((const float*)hs)[j];
        const float hv = (1.f - z) * n + z * hj;
        g_concat[H + j] = hv;     // h_new half of concat
        g_concat[j]     = 0.f;    // zero ctx half for atomic accumulation
        out_h[j]        = hv;     // second output tensor
    }
}

// ---------------- 2) attention scores: warp-per-row float4, 8 rows/block ----------------
__global__ void __launch_bounds__(256) scores_kernel(const float* __restrict__ enc)
{
    __shared__ float4 hshr[H / 4];
    const int tid = threadIdx.x;
    const float4* hc = (const float4*)(&g_concat[H]);
    hshr[tid] = hc[tid];                 // 256 float4 = 1024 floats
    __syncthreads();
    const int warp = tid >> 5, lane = tid & 31;
    const int row = blockIdx.x * 8 + warp;      // grid = L/8 = 512
    const float4* er = (const float4*)(enc + (size_t)row * H);
    float acc = 0.f;
#pragma unroll
    for (int i = 0; i < 8; i++) {
        const float4 e4 = er[lane + 32 * i];
        const float4 h4 = hshr[lane + 32 * i];
        acc += e4.x * h4.x + e4.y * h4.y + e4.z * h4.z + e4.w * h4.w;
    }
    acc = warp_sum(acc);
    if (lane == 0) g_scores[row] = acc;
}

// ---------------- 3) softmax over L=4096 (single block) ----------------
__global__ void __launch_bounds__(1024) softmax_kernel()
{
    __shared__ float sred[32];
    __shared__ float bcast;
    const int tid = threadIdx.x;
    float v[4];
    float m = -INFINITY;
#pragma unroll
    for (int i = 0; i < 4; i++) { v[i] = g_scores[tid + 1024 * i]; m = fmaxf(m, v[i]); }
    m = warp_max(m);
    if ((tid & 31) == 0) sred[tid >> 5] = m;
    __syncthreads();
    if (tid < 32) { float t = sred[tid]; t = warp_max(t); if (tid == 0) bcast = t; }
    __syncthreads();
    const float M = bcast;
    float e[4];
    float s = 0.f;
#pragma unroll
    for (int i = 0; i < 4; i++) { e[i] = __expf(v[i] - M); s += e[i]; }
    s = warp_sum(s);
    if ((tid & 31) == 0) sred[tid >> 5] = s;
    __syncthreads();
    if (tid < 32) { float t = sred[tid]; t = warp_sum(t); if (tid == 0) bcast = t; }
    __syncthreads();
    const float inv = 1.f / bcast;
#pragma unroll
    for (int i = 0; i < 4; i++) g_attn[tid + 1024 * i] = e[i] * inv;
}

// ---------------- 4) ctx = attn @ enc : 512 blocks × 8 rows, float4 columns ----------------
// 8 independent float4 loads per thread (fits in registers -> real MLP=8),
// 512 blocks ≈ 3.5/SM: enough warps chip-wide to cover DRAM latency.
__global__ void __launch_bounds__(256) ctx_kernel(const float* __restrict__ enc)
{
    __shared__ float aw[8];
    const int tid = threadIdx.x;
    const int l0 = blockIdx.x * 8;           // grid = L/8 = 512
    if (tid < 8) aw[tid] = g_attn[l0 + tid];
    __syncthreads();
    const float4* e4 = (const float4*)enc;   // 256 float4 per row
    float ax = 0.f, ay = 0.f, az = 0.f, awc = 0.f;
#pragma unroll
    for (int l = 0; l < 8; l++) {
        const float a = aw[l];
        const float4 v = e4[(size_t)(l0 + l) * 256 + tid];
        ax += a * v.x; ay += a * v.y; az += a * v.z; awc += a * v.w;
    }
    float* c = &g_concat[tid * 4];
    atomicAdd(c + 0, ax);
    atomicAdd(c + 1, ay);
    atomicAdd(c + 2, az);
    atomicAdd(c + 3, awc);
}

// ---------------- 5) logits: warp-per-row float4 matvec (the 412 MB pass) ----------------
__global__ void __launch_bounds__(256) logits_kernel(
    const float* __restrict__ out_w, const float* __restrict__ out_b,
    float* __restrict__ logits)
{
    __shared__ float4 cs[512];          // concat (2048 floats) as float4
    const int tid = threadIdx.x;
    const float4* cc = (const float4*)g_concat;
    cs[tid]       = cc[tid];
    cs[tid + 256] = cc[tid + 256];
    __syncthreads();
    const int warp = tid >> 5, lane = tid & 31;
    const int row = blockIdx.x * 8 + warp;
    if (row >= V) return;
    const float4* wr = (const float4*)(out_w + (size_t)row * (2 * H));
    float acc = 0.f;
#pragma unroll
    for (int i = 0; i < 16; i++) {
        const float4 w4 = wr[lane + 32 * i];
        const float4 c4 = cs[lane + 32 * i];
        acc += w4.x * c4.x + w4.y * c4.y + w4.z * c4.z + w4.w * c4.w;
    }
    acc = warp_sum(acc);
    if (lane == 0) logits[row] = acc + out_b[row];
}

// ---------------- 6) LSE partials (64 blocks) ----------------
__global__ void __launch_bounds__(256) lse_part_kernel(const float* __restrict__ logits)
{
    __shared__ float sred[8];
    __shared__ float bcast;
    const int tid = threadIdx.x;
    const int gtid = blockIdx.x * 256 + tid;
    float v[4];
    float m = -INFINITY;
#pragma unroll
    for (int i = 0; i < 4; i++) {
        const int idx = gtid + 16384 * i;
        v[i] = (idx < V) ? logits[idx] : -INFINITY;
        m = fmaxf(m, v[i]);
    }
    m = warp_max(m);
    if ((tid & 31) == 0) sred[tid >> 5] = m;
    __syncthreads();
    if (tid < 8) {
        float t = sred[tid];
#pragma unroll
        for (int o = 4; o > 0; o >>= 1) t = fmaxf(t, __shfl_down_sync(0xFFu, t, o));
        if (tid == 0) bcast = t;
    }
    __syncthreads();
    const float M = bcast;
    float s = 0.f;
#pragma unroll
    for (int i = 0; i < 4; i++) s += __expf(v[i] - M);   // -inf -> 0
    s = warp_sum(s);
    if ((tid & 31) == 0) sred[tid >> 5] = s;
    __syncthreads();
    if (tid < 8) {
        float t = sred[tid];
#pragma unroll
        for (int o = 4; o > 0; o >>= 1) t += __shfl_down_sync(0xFFu, t, o);
        if (tid == 0) { g_part[2 * blockIdx.x] = M; g_part[2 * blockIdx.x + 1] = t; }
    }
}

// ---------------- 7) merge 64 partials ----------------
__global__ void lse_merge_kernel()
{
    float M = -INFINITY;
    for (int i = 0; i < 64; i++) M = fmaxf(M, g_part[2 * i]);
    float S = 0.f;
    for (int i = 0; i < 64; i++) S += g_part[2 * i + 1] * __expf(g_part[2 * i] - M);
    g_lse = M + logf(S);
}

// ---------------- 8) finalize log-softmax in place ----------------
__global__ void __launch_bounds__(256) finalize_kernel(float* __restrict__ logits)
{
    const int v = blockIdx.x * 256 + threadIdx.x;
    if (v < V) logits[v] -= g_lse;
}

// ---------------- launcher ----------------
extern "C" void kernel_launch(void* const* d_in, const int* in_sizes, int n_in,
                              void* d_out, int out_size)
{
    const int*   inp   = (const int*)  d_in[0];   // token id (read low 32 bits)
    const float* hidden= (const float*)d_in[1];
    const float* enc   = (const float*)d_in[2];
    const float* emb   = (const float*)d_in[3];
    const float* w_ih  = (const float*)d_in[4];
    const float* w_hh  = (const float*)d_in[5];
    const float* b_ih  = (const float*)d_in[6];
    const float* b_hh  = (const float*)d_in[7];
    const float* out_w = (const float*)d_in[8];
    const float* out_b = (const float*)d_in[9];
    float* out = (float*)d_out;                   // [0..V) log-probs, [V..V+H) h_new

    gru_kernel<<<H, 128>>>(inp, hidden, emb, w_ih, w_hh, b_ih, b_hh, out + V);
    scores_kernel<<<L / 8, 256>>>(enc);
    softmax_kernel<<<1, 1024>>>();
    ctx_kernel<<<L / 8, 256>>>(enc);
    logits_kernel<<<(V + 7) / 8, 256>>>(out_w, out_b, out);
    lse_part_kernel<<<64, 256>>>(out);
    lse_merge_kernel<<<1, 1>>>();
    finalize_kernel<<<(V + 255) / 256, 256>>>(out);
}

// round 4
// speedup vs baseline: 1.2729x; 1.2729x over previous
#include <cuda_runtime.h>
#include <math.h>

#define H 1024
#define V 50257
#define L 4096

// ---------------- device scratch (no allocations allowed) ----------------
__device__ float g_concat[2 * H];        // [0..H) = ctx, [H..2H) = h_new
__device__ float4 g_ctx_part4[256 * 256]; // 256 partials x 1024 cols (as float4) = 1 MB
__device__ float g_scores[L];
__device__ float g_attn[L];
__device__ float g_part[128];            // 64 (max, sumexp) pairs
__device__ float g_lse;

// ---------------- helpers ----------------
__device__ __forceinline__ float warp_sum(float v) {
#pragma unroll
    for (int o = 16; o > 0; o >>= 1) v += __shfl_down_sync(0xFFFFFFFFu, v, o);
    return v;
}
__device__ __forceinline__ float warp_max(float v) {
#pragma unroll
    for (int o = 16; o > 0; o >>= 1) v = fmaxf(v, __shfl_down_sync(0xFFFFFFFFu, v, o));
    return v;
}

// ---------------- 1) GRU cell: one block per output element j (float4 loads) --------
__global__ void __launch_bounds__(128) gru_kernel(
    const int* __restrict__ inp, const float* __restrict__ hidden,
    const float* __restrict__ embedding,
    const float* __restrict__ w_ih, const float* __restrict__ w_hh,
    const float* __restrict__ b_ih, const float* __restrict__ b_hh,
    float* __restrict__ out_h)
{
    __shared__ float4 xs[H / 4];
    __shared__ float4 hs[H / 4];
    __shared__ float red[6][4];
    const int j = blockIdx.x;
    const int tid = threadIdx.x;
    const int idx = inp[0];   // low 32 bits of the (int64) token id — LE safe

    const float4* emb4 = (const float4*)(embedding + (size_t)idx * H);
    const float4* hid4 = (const float4*)hidden;
    xs[tid]       = emb4[tid];        xs[tid + 128] = emb4[tid + 128];
    hs[tid]       = hid4[tid];        hs[tid + 128] = hid4[tid + 128];
    __syncthreads();

    const float4* wi0 = (const float4*)(w_ih + (size_t)j * H);
    const float4* wi1 = (const float4*)(w_ih + (size_t)(j + H) * H);
    const float4* wi2 = (const float4*)(w_ih + (size_t)(j + 2 * H) * H);
    const float4* wh0 = (const float4*)(w_hh + (size_t)j * H);
    const float4* wh1 = (const float4*)(w_hh + (size_t)(j + H) * H);
    const float4* wh2 = (const float4*)(w_hh + (size_t)(j + 2 * H) * H);

    float a0 = 0.f, a1 = 0.f, a2 = 0.f, a3 = 0.f, a4 = 0.f, a5 = 0.f;
#pragma unroll
    for (int p = 0; p < 2; p++) {
        const int k = tid + 128 * p;
        const float4 xv = xs[k], hv = hs[k];
        float4 w;
        w = wi0[k]; a0 += w.x * xv.x + w.y * xv.y + w.z * xv.z + w.w * xv.w;
        w = wi1[k]; a1 += w.x * xv.x + w.y * xv.y + w.z * xv.z + w.w * xv.w;
        w = wi2[k]; a2 += w.x * xv.x + w.y * xv.y + w.z * xv.z + w.w * xv.w;
        w = wh0[k]; a3 += w.x * hv.x + w.y * hv.y + w.z * hv.z + w.w * hv.w;
        w = wh1[k]; a4 += w.x * hv.x + w.y * hv.y + w.z * hv.z + w.w * hv.w;
        w = wh2[k]; a5 += w.x * hv.x + w.y * hv.y + w.z * hv.z + w.w * hv.w;
    }
    a0 = warp_sum(a0); a1 = warp_sum(a1); a2 = warp_sum(a2);
    a3 = warp_sum(a3); a4 = warp_sum(a4); a5 = warp_sum(a5);
    const int warp = tid >> 5, lane = tid & 31;
    if (lane == 0) {
        red[0][warp] = a0; red[1][warp] = a1; red[2][warp] = a2;
        red[3][warp] = a3; red[4][warp] = a4; red[5][warp] = a5;
    }
    __syncthreads();
    if (tid == 0) {
        float s[6];
#pragma unroll
        for (int q = 0; q < 6; q++) s[q] = red[q][0] + red[q][1] + red[q][2] + red[q][3];
        const float i_r = s[0] + b_ih[j];
        const float i_z = s[1] + b_ih[j + H];
        const float i_n = s[2] + b_ih[j + 2 * H];
        const float h_r = s[3] + b_hh[j];
        const float h_z = s[4] + b_hh[j + H];
        const float h_n = s[5] + b_hh[j + 2 * H];
        const float r = 1.f / (1.f + __expf(-(i_r + h_r)));
        const float z = 1.f / (1.f + __expf(-(i_z + h_z)));
        const float n = tanhf(i_n + r * h_n);
        const float hj = ((const float*)hs)[j];
        const float hv = (1.f - z) * n + z * hj;
        g_concat[H + j] = hv;     // h_new half of concat
        out_h[j]        = hv;     // second output tensor
    }
}

// ---------------- 2) attention scores: warp-per-row float4, 8 rows/block ----------------
__global__ void __launch_bounds__(256) scores_kernel(const float* __restrict__ enc)
{
    __shared__ float4 hshr[H / 4];
    const int tid = threadIdx.x;
    const float4* hc = (const float4*)(&g_concat[H]);
    hshr[tid] = hc[tid];                 // 256 float4 = 1024 floats
    __syncthreads();
    const int warp = tid >> 5, lane = tid & 31;
    const int row = blockIdx.x * 8 + warp;      // grid = L/8 = 512
    const float4* er = (const float4*)(enc + (size_t)row * H);
    float acc = 0.f;
#pragma unroll
    for (int i = 0; i < 8; i++) {
        const float4 e4 = er[lane + 32 * i];
        const float4 h4 = hshr[lane + 32 * i];
        acc += e4.x * h4.x + e4.y * h4.y + e4.z * h4.z + e4.w * h4.w;
    }
    acc = warp_sum(acc);
    if (lane == 0) g_scores[row] = acc;
}

// ---------------- 3) softmax over L=4096 (single block) ----------------
__global__ void __launch_bounds__(1024) softmax_kernel()
{
    __shared__ float sred[32];
    __shared__ float bcast;
    const int tid = threadIdx.x;
    float v[4];
    float m = -INFINITY;
#pragma unroll
    for (int i = 0; i < 4; i++) { v[i] = g_scores[tid + 1024 * i]; m = fmaxf(m, v[i]); }
    m = warp_max(m);
    if ((tid & 31) == 0) sred[tid >> 5] = m;
    __syncthreads();
    if (tid < 32) { float t = sred[tid]; t = warp_max(t); if (tid == 0) bcast = t; }
    __syncthreads();
    const float M = bcast;
    float e[4];
    float s = 0.f;
#pragma unroll
    for (int i = 0; i < 4; i++) { e[i] = __expf(v[i] - M); s += e[i]; }
    s = warp_sum(s);
    if ((tid & 31) == 0) sred[tid >> 5] = s;
    __syncthreads();
    if (tid < 32) { float t = sred[tid]; t = warp_sum(t); if (tid == 0) bcast = t; }
    __syncthreads();
    const float inv = 1.f / bcast;
#pragma unroll
    for (int i = 0; i < 4; i++) g_attn[tid + 1024 * i] = e[i] * inv;
}

// ---------------- 4a) ctx stage A: 256 blocks x 16 rows -> private partials, NO atomics --
__global__ void __launch_bounds__(256) ctx_part_kernel(const float* __restrict__ enc)
{
    __shared__ float aw[16];
    const int tid = threadIdx.x;
    const int l0 = blockIdx.x * 16;          // grid = L/16 = 256
    if (tid < 16) aw[tid] = g_attn[l0 + tid];
    __syncthreads();
    const float4* e4 = (const float4*)enc;   // 256 float4 per row
    float4 acc0 = make_float4(0.f, 0.f, 0.f, 0.f);
    float4 acc1 = make_float4(0.f, 0.f, 0.f, 0.f);
#pragma unroll
    for (int l = 0; l < 8; l++) {
        const float a = aw[l];
        const float4 v = e4[(size_t)(l0 + l) * 256 + tid];
        acc0.x += a * v.x; acc0.y += a * v.y; acc0.z += a * v.z; acc0.w += a * v.w;
    }
#pragma unroll
    for (int l = 8; l < 16; l++) {
        const float a = aw[l];
        const float4 v = e4[(size_t)(l0 + l) * 256 + tid];
        acc1.x += a * v.x; acc1.y += a * v.y; acc1.z += a * v.z; acc1.w += a * v.w;
    }
    acc0.x += acc1.x; acc0.y += acc1.y; acc0.z += acc1.z; acc0.w += acc1.w;
    g_ctx_part4[blockIdx.x * 256 + tid] = acc0;   // coalesced private write
}

// ---------------- 4b) ctx stage B: reduce 256 partials, each column owned by 1 thread --
__global__ void __launch_bounds__(256) ctx_reduce_kernel()
{
    __shared__ float4 s[256];
    const int tid = threadIdx.x;
    const int b = blockIdx.x;                // 16 blocks, each owns 64 cols (16 float4)
    const int c4 = tid & 15;                 // float4 index within the block's span
    const int pg = tid >> 4;                 // 16 partial groups
    float4 acc = make_float4(0.f, 0.f, 0.f, 0.f);
#pragma unroll
    for (int k = 0; k < 16; k++) {
        const int p = pg + 16 * k;
        const float4 v = g_ctx_part4[p * 256 + b * 16 + c4];
        acc.x += v.x; acc.y += v.y; acc.z += v.z; acc.w += v.w;
    }
    s[tid] = acc;
    __syncthreads();
    if (pg == 0) {
        float4 t = s[c4];
#pragma unroll
        for (int k = 1; k < 16; k++) {
            const float4 v = s[k * 16 + c4];
            t.x += v.x; t.y += v.y; t.z += v.z; t.w += v.w;
        }
        ((float4*)g_concat)[b * 16 + c4] = t;   // exclusive owner: plain store
    }
}

// ---------------- 5) logits: warp-per-row float4 matvec (the 412 MB pass) ----------------
__global__ void __launch_bounds__(256) logits_kernel(
    const float* __restrict__ out_w, const float* __restrict__ out_b,
    float* __restrict__ logits)
{
    __shared__ float4 cs[512];          // concat (2048 floats) as float4
    const int tid = threadIdx.x;
    const float4* cc = (const float4*)g_concat;
    cs[tid]       = cc[tid];
    cs[tid + 256] = cc[tid + 256];
    __syncthreads();
    const int warp = tid >> 5, lane = tid & 31;
    const int row = blockIdx.x * 8 + warp;
    if (row >= V) return;
    const float4* wr = (const float4*)(out_w + (size_t)row * (2 * H));
    float acc = 0.f;
#pragma unroll
    for (int i = 0; i < 16; i++) {
        const float4 w4 = __ldcs(&wr[lane + 32 * i]);   // streaming: don't pollute L2
        const float4 c4 = cs[lane + 32 * i];
        acc += w4.x * c4.x + w4.y * c4.y + w4.z * c4.z + w4.w * c4.w;
    }
    acc = warp_sum(acc);
    if (lane == 0) logits[row] = acc + out_b[row];
}

// ---------------- 6) LSE partials (64 blocks) ----------------
__global__ void __launch_bounds__(256) lse_part_kernel(const float* __restrict__ logits)
{
    __shared__ float sred[8];
    __shared__ float bcast;
    const int tid = threadIdx.x;
    const int gtid = blockIdx.x * 256 + tid;
    float v[4];
    float m = -INFINITY;
#pragma unroll
    for (int i = 0; i < 4; i++) {
        const int idx = gtid + 16384 * i;
        v[i] = (idx < V) ? logits[idx] : -INFINITY;
        m = fmaxf(m, v[i]);
    }
    m = warp_max(m);
    if ((tid & 31) == 0) sred[tid >> 5] = m;
    __syncthreads();
    if (tid < 8) {
        float t = sred[tid];
#pragma unroll
        for (int o = 4; o > 0; o >>= 1) t = fmaxf(t, __shfl_down_sync(0xFFu, t, o));
        if (tid == 0) bcast = t;
    }
    __syncthreads();
    const float M = bcast;
    float s = 0.f;
#pragma unroll
    for (int i = 0; i < 4; i++) s += __expf(v[i] - M);   // -inf -> 0
    s = warp_sum(s);
    if ((tid & 31) == 0) sred[tid >> 5] = s;
    __syncthreads();
    if (tid < 8) {
        float t = sred[tid];
#pragma unroll
        for (int o = 4; o > 0; o >>= 1) t += __shfl_down_sync(0xFFu, t, o);
        if (tid == 0) { g_part[2 * blockIdx.x] = M; g_part[2 * blockIdx.x + 1] = t; }
    }
}

// ---------------- 7) merge 64 partials ----------------
__global__ void lse_merge_kernel()
{
    float M = -INFINITY;
    for (int i = 0; i < 64; i++) M = fmaxf(M, g_part[2 * i]);
    float S = 0.f;
    for (int i = 0; i < 64; i++) S += g_part[2 * i + 1] * __expf(g_part[2 * i] - M);
    g_lse = M + logf(S);
}

// ---------------- 8) finalize log-softmax in place ----------------
__global__ void __launch_bounds__(256) finalize_kernel(float* __restrict__ logits)
{
    const int v = blockIdx.x * 256 + threadIdx.x;
    if (v < V) logits[v] -= g_lse;
}

// ---------------- launcher ----------------
extern "C" void kernel_launch(void* const* d_in, const int* in_sizes, int n_in,
                              void* d_out, int out_size)
{
    const int*   inp   = (const int*)  d_in[0];   // token id (read low 32 bits)
    const float* hidden= (const float*)d_in[1];
    const float* enc   = (const float*)d_in[2];
    const float* emb   = (const float*)d_in[3];
    const float* w_ih  = (const float*)d_in[4];
    const float* w_hh  = (const float*)d_in[5];
    const float* b_ih  = (const float*)d_in[6];
    const float* b_hh  = (const float*)d_in[7];
    const float* out_w = (const float*)d_in[8];
    const float* out_b = (const float*)d_in[9];
    float* out = (float*)d_out;                   // [0..V) log-probs, [V..V+H) h_new

    gru_kernel<<<H, 128>>>(inp, hidden, emb, w_ih, w_hh, b_ih, b_hh, out + V);
    scores_kernel<<<L / 8, 256>>>(enc);
    softmax_kernel<<<1, 1024>>>();
    ctx_part_kernel<<<L / 16, 256>>>(enc);
    ctx_reduce_kernel<<<16, 256>>>();
    logits_kernel<<<(V + 7) / 8, 256>>>(out_w, out_b, out);
    lse_part_kernel<<<64, 256>>>(out);
    lse_merge_kernel<<<1, 1>>>();
    finalize_kernel<<<(V + 255) / 256, 256>>>(out);
}

// round 5
// speedup vs baseline: 1.2744x; 1.0012x over previous
#include <cuda_runtime.h>
#include <math.h>

#define H 1024
#define V 50257
#define L 4096
#define NPART 512          // ctx partials (one per ctx_part block)

// ---------------- device scratch (no allocations allowed) ----------------
__device__ float g_concat[2 * H];            // [0..H) = ctx, [H..2H) = h_new
__device__ float4 g_ctx_part4[NPART * 256];  // 512 partials x 1024 cols (float4) = 2 MB
__device__ float g_scores[L];
__device__ float g_spart[2 * (L / 8)];       // 512 per-block (max, sumexp) pairs for attn softmax
__device__ float g_part[128];                // 64 (max, sumexp) pairs for logit LSE
__device__ float g_lse;

// ---------------- helpers ----------------
__device__ __forceinline__ float warp_sum(float v) {
#pragma unroll
    for (int o = 16; o > 0; o >>= 1) v += __shfl_down_sync(0xFFFFFFFFu, v, o);
    return v;
}
__device__ __forceinline__ float warp_max(float v) {
#pragma unroll
    for (int o = 16; o > 0; o >>= 1) v = fmaxf(v, __shfl_down_sync(0xFFFFFFFFu, v, o));
    return v;
}

// ---------------- 1) GRU cell: one block per output element j (float4 loads) --------
__global__ void __launch_bounds__(128) gru_kernel(
    const int* __restrict__ inp, const float* __restrict__ hidden,
    const float* __restrict__ embedding,
    const float* __restrict__ w_ih, const float* __restrict__ w_hh,
    const float* __restrict__ b_ih, const float* __restrict__ b_hh,
    float* __restrict__ out_h)
{
    __shared__ float4 xs[H / 4];
    __shared__ float4 hs[H / 4];
    __shared__ float red[6][4];
    const int j = blockIdx.x;
    const int tid = threadIdx.x;
    const int idx = inp[0];   // low 32 bits of the (int64) token id — LE safe

    const float4* emb4 = (const float4*)(embedding + (size_t)idx * H);
    const float4* hid4 = (const float4*)hidden;
    xs[tid]       = emb4[tid];        xs[tid + 128] = emb4[tid + 128];
    hs[tid]       = hid4[tid];        hs[tid + 128] = hid4[tid + 128];
    __syncthreads();

    const float4* wi0 = (const float4*)(w_ih + (size_t)j * H);
    const float4* wi1 = (const float4*)(w_ih + (size_t)(j + H) * H);
    const float4* wi2 = (const float4*)(w_ih + (size_t)(j + 2 * H) * H);
    const float4* wh0 = (const float4*)(w_hh + (size_t)j * H);
    const float4* wh1 = (const float4*)(w_hh + (size_t)(j + H) * H);
    const float4* wh2 = (const float4*)(w_hh + (size_t)(j + 2 * H) * H);

    float a0 = 0.f, a1 = 0.f, a2 = 0.f, a3 = 0.f, a4 = 0.f, a5 = 0.f;
#pragma unroll
    for (int p = 0; p < 2; p++) {
        const int k = tid + 128 * p;
        const float4 xv = xs[k], hv = hs[k];
        float4 w;
        w = wi0[k]; a0 += w.x * xv.x + w.y * xv.y + w.z * xv.z + w.w * xv.w;
        w = wi1[k]; a1 += w.x * xv.x + w.y * xv.y + w.z * xv.z + w.w * xv.w;
        w = wi2[k]; a2 += w.x * xv.x + w.y * xv.y + w.z * xv.z + w.w * xv.w;
        w = wh0[k]; a3 += w.x * hv.x + w.y * hv.y + w.z * hv.z + w.w * hv.w;
        w = wh1[k]; a4 += w.x * hv.x + w.y * hv.y + w.z * hv.z + w.w * hv.w;
        w = wh2[k]; a5 += w.x * hv.x + w.y * hv.y + w.z * hv.z + w.w * hv.w;
    }
    a0 = warp_sum(a0); a1 = warp_sum(a1); a2 = warp_sum(a2);
    a3 = warp_sum(a3); a4 = warp_sum(a4); a5 = warp_sum(a5);
    const int warp = tid >> 5, lane = tid & 31;
    if (lane == 0) {
        red[0][warp] = a0; red[1][warp] = a1; red[2][warp] = a2;
        red[3][warp] = a3; red[4][warp] = a4; red[5][warp] = a5;
    }
    __syncthreads();
    if (tid == 0) {
        float s[6];
#pragma unroll
        for (int q = 0; q < 6; q++) s[q] = red[q][0] + red[q][1] + red[q][2] + red[q][3];
        const float i_r = s[0] + b_ih[j];
        const float i_z = s[1] + b_ih[j + H];
        const float i_n = s[2] + b_ih[j + 2 * H];
        const float h_r = s[3] + b_hh[j];
        const float h_z = s[4] + b_hh[j + H];
        const float h_n = s[5] + b_hh[j + 2 * H];
        const float r = 1.f / (1.f + __expf(-(i_r + h_r)));
        const float z = 1.f / (1.f + __expf(-(i_z + h_z)));
        const float n = tanhf(i_n + r * h_n);
        const float hj = ((const float*)hs)[j];
        const float hv = (1.f - z) * n + z * hj;
        g_concat[H + j] = hv;     // h_new half of concat
        out_h[j]        = hv;     // second output tensor
    }
}

// ---------------- 2) scores + per-block softmax partials (max, sumexp) ----------------
__global__ void __launch_bounds__(256) scores_kernel(const float* __restrict__ enc)
{
    __shared__ float4 hshr[H / 4];
    __shared__ float sarr[8];
    const int tid = threadIdx.x;
    const float4* hc = (const float4*)(&g_concat[H]);
    hshr[tid] = hc[tid];                 // 256 float4 = 1024 floats
    __syncthreads();
    const int warp = tid >> 5, lane = tid & 31;
    const int row = blockIdx.x * 8 + warp;      // grid = L/8 = 512
    const float4* er = (const float4*)(enc + (size_t)row * H);
    float acc = 0.f;
#pragma unroll
    for (int i = 0; i < 8; i++) {
        const float4 e4 = er[lane + 32 * i];
        const float4 h4 = hshr[lane + 32 * i];
        acc += e4.x * h4.x + e4.y * h4.y + e4.z * h4.z + e4.w * h4.w;
    }
    acc = warp_sum(acc);
    if (lane == 0) { g_scores[row] = acc; sarr[warp] = acc; }
    __syncthreads();
    if (tid == 0) {
        float m = sarr[0];
#pragma unroll
        for (int k = 1; k < 8; k++) m = fmaxf(m, sarr[k]);
        float s = 0.f;
#pragma unroll
        for (int k = 0; k < 8; k++) s += __expf(sarr[k] - m);
        g_spart[2 * blockIdx.x]     = m;
        g_spart[2 * blockIdx.x + 1] = s;
    }
}

// ---------------- 3) ctx stage A: merge softmax partials inline, 512 blocks x 8 rows ----
__global__ void __launch_bounds__(256) ctx_part_kernel(const float* __restrict__ enc)
{
    __shared__ float sm[8], ss[8];
    __shared__ float wts[8];
    const int tid = threadIdx.x;
    const int warp = tid >> 5, lane = tid & 31;
    const int l0 = blockIdx.x * 8;           // grid = L/8 = 512

    // ---- merge the 512 (max,sumexp) pairs: 2 per thread, then tree ----
    float m = g_spart[2 * tid], s = g_spart[2 * tid + 1];
    {
        const float m2 = g_spart[2 * (tid + 256)], s2 = g_spart[2 * (tid + 256) + 1];
        const float nm = fmaxf(m, m2);
        s = s * __expf(m - nm) + s2 * __expf(m2 - nm);
        m = nm;
    }
#pragma unroll
    for (int o = 16; o > 0; o >>= 1) {
        const float om = __shfl_down_sync(0xFFFFFFFFu, m, o);
        const float os = __shfl_down_sync(0xFFFFFFFFu, s, o);
        const float nm = fmaxf(m, om);
        s = s * __expf(m - nm) + os * __expf(om - nm);
        m = nm;
    }
    if (lane == 0) { sm[warp] = m; ss[warp] = s; }
    __syncthreads();
    if (tid < 8) {
        float M = sm[0], S = ss[0];
#pragma unroll
        for (int k = 1; k < 8; k++) {
            const float nm = fmaxf(M, sm[k]);
            S = S * __expf(M - nm) + ss[k] * __expf(sm[k] - nm);
            M = nm;
        }
        wts[tid] = __expf(g_scores[l0 + tid] - M) / S;   // this block's 8 attn weights
    }
    __syncthreads();

    // ---- weighted row accumulation: 8 independent float4 loads ----
    const float4* e4 = (const float4*)enc;   // 256 float4 per row
    float4 acc = make_float4(0.f, 0.f, 0.f, 0.f);
#pragma unroll
    for (int l = 0; l < 8; l++) {
        const float a = wts[l];
        const float4 v = e4[(size_t)(l0 + l) * 256 + tid];
        acc.x += a * v.x; acc.y += a * v.y; acc.z += a * v.z; acc.w += a * v.w;
    }
    g_ctx_part4[blockIdx.x * 256 + tid] = acc;   // coalesced private write
}

// ---------------- 4) ctx stage B: reduce 512 partials, exclusive column owners ----------
__global__ void __launch_bounds__(256) ctx_reduce_kernel()
{
    __shared__ float4 s[256];
    const int tid = threadIdx.x;
    const int b = blockIdx.x;                // 16 blocks, each owns 64 cols (16 float4)
    const int c4 = tid & 15;                 // float4 index within the block's span
    const int pg = tid >> 4;                 // 16 partial groups
    float4 acc = make_float4(0.f, 0.f, 0.f, 0.f);
#pragma unroll
    for (int k = 0; k < NPART / 16; k++) {
        const int p = pg + 16 * k;
        const float4 v = g_ctx_part4[p * 256 + b * 16 + c4];
        acc.x += v.x; acc.y += v.y; acc.z += v.z; acc.w += v.w;
    }
    s[tid] = acc;
    __syncthreads();
    if (pg == 0) {
        float4 t = s[c4];
#pragma unroll
        for (int k = 1; k < 16; k++) {
            const float4 v = s[k * 16 + c4];
            t.x += v.x; t.y += v.y; t.z += v.z; t.w += v.w;
        }
        ((float4*)g_concat)[b * 16 + c4] = t;   // exclusive owner: plain store
    }
}

// ---------------- 5) logits: warp-per-row float4 matvec (the 412 MB pass) ----------------
__global__ void __launch_bounds__(512) logits_kernel(
    const float* __restrict__ out_w, const float* __restrict__ out_b,
    float* __restrict__ logits)
{
    __shared__ float4 cs[512];          // concat (2048 floats) as float4
    const int tid = threadIdx.x;
    const float4* cc = (const float4*)g_concat;
    if (tid < 512) cs[tid] = cc[tid];
    __syncthreads();
    const int warp = tid >> 5, lane = tid & 31;
    const int row = blockIdx.x * 16 + warp;
    if (row >= V) return;
    const float4* wr = (const float4*)(out_w + (size_t)row * (2 * H));
    float acc = 0.f;
#pragma unroll
    for (int i = 0; i < 16; i++) {
        const float4 w4 = __ldcs(&wr[lane + 32 * i]);   // streaming: don't pollute L2
        const float4 c4 = cs[lane + 32 * i];
        acc += w4.x * c4.x + w4.y * c4.y + w4.z * c4.z + w4.w * c4.w;
    }
    acc = warp_sum(acc);
    if (lane == 0) logits[row] = acc + out_b[row];
}

// ---------------- 6) LSE partials (64 blocks) ----------------
__global__ void __launch_bounds__(256) lse_part_kernel(const float* __restrict__ logits)
{
    __shared__ float sred[8];
    __shared__ float bcast;
    const int tid = threadIdx.x;
    const int gtid = blockIdx.x * 256 + tid;
    float v[4];
    float m = -INFINITY;
#pragma unroll
    for (int i = 0; i < 4; i++) {
        const int idx = gtid + 16384 * i;
        v[i] = (idx < V) ? logits[idx] : -INFINITY;
        m = fmaxf(m, v[i]);
    }
    m = warp_max(m);
    if ((tid & 31) == 0) sred[tid >> 5] = m;
    __syncthreads();
    if (tid < 8) {
        float t = sred[tid];
#pragma unroll
        for (int o = 4; o > 0; o >>= 1) t = fmaxf(t, __shfl_down_sync(0xFFu, t, o));
        if (tid == 0) bcast = t;
    }
    __syncthreads();
    const float M = bcast;
    float s = 0.f;
#pragma unroll
    for (int i = 0; i < 4; i++) s += __expf(v[i] - M);   // -inf -> 0
    s = warp_sum(s);
    if ((tid & 31) == 0) sred[tid >> 5] = s;
    __syncthreads();
    if (tid < 8) {
        float t = sred[tid];
#pragma unroll
        for (int o = 4; o > 0; o >>= 1) t += __shfl_down_sync(0xFFu, t, o);
        if (tid == 0) { g_part[2 * blockIdx.x] = M; g_part[2 * blockIdx.x + 1] = t; }
    }
}

// ---------------- 7) finalize: per-block redundant merge of 64 partials, then subtract --
__global__ void __launch_bounds__(256) finalize_kernel(float* __restrict__ logits)
{
    __shared__ float sm[2], ss[2];
    __shared__ float lse_s;
    const int tid = threadIdx.x;
    const int warp = tid >> 5, lane = tid & 31;
    // threads 0..63 load the 64 pairs; merge with (max, scaled-sum) tree
    float m = -INFINITY, s = 0.f;
    if (tid < 64) { m = g_part[2 * tid]; s = g_part[2 * tid + 1]; }
#pragma unroll
    for (int o = 16; o > 0; o >>= 1) {
        const float om = __shfl_down_sync(0xFFFFFFFFu, m, o);
        const float os = __shfl_down_sync(0xFFFFFFFFu, s, o);
        const float nm = fmaxf(m, om);
        s = s * __expf(m - nm) + os * __expf(om - nm);
        m = nm;
    }
    if (warp < 2 && lane == 0) { sm[warp] = m; ss[warp] = s; }
    __syncthreads();
    if (tid == 0) {
        const float nm = fmaxf(sm[0], sm[1]);
        const float S = ss[0] * __expf(sm[0] - nm) + ss[1] * __expf(sm[1] - nm);
        lse_s = nm + logf(S);
    }
    __syncthreads();
    const int v = blockIdx.x * 256 + tid;
    if (v < V) logits[v] -= lse_s;
}

// ---------------- launcher ----------------
extern "C" void kernel_launch(void* const* d_in, const int* in_sizes, int n_in,
                              void* d_out, int out_size)
{
    const int*   inp   = (const int*)  d_in[0];   // token id (read low 32 bits)
    const float* hidden= (const float*)d_in[1];
    const float* enc   = (const float*)d_in[2];
    const float* emb   = (const float*)d_in[3];
    const float* w_ih  = (const float*)d_in[4];
    const float* w_hh  = (const float*)d_in[5];
    const float* b_ih  = (const float*)d_in[6];
    const float* b_hh  = (const float*)d_in[7];
    const float* out_w = (const float*)d_in[8];
    const float* out_b = (const float*)d_in[9];
    float* out = (float*)d_out;                   // [0..V) log-probs, [V..V+H) h_new

    gru_kernel<<<H, 128>>>(inp, hidden, emb, w_ih, w_hh, b_ih, b_hh, out + V);
    scores_kernel<<<L / 8, 256>>>(enc);
    ctx_part_kernel<<<L / 8, 256>>>(enc);
    ctx_reduce_kernel<<<16, 256>>>();
    logits_kernel<<<(V + 15) / 16, 512>>>(out_w, out_b, out);
    lse_part_kernel<<<64, 256>>>(out);
    finalize_kernel<<<(V + 255) / 256, 256>>>(out);
}